// round 14
// baseline (speedup 1.0000x reference)
#include <cuda_runtime.h>
#include <cuda_fp16.h>
#include <math.h>

#define NND 100000
#define NE  1600000
#define HID 128
#define OUTC 64
#define ENC_M 8
#define CHUNK 64

struct __align__(8) EdgeP { int src; float w; };

// ---- scratch (static device globals; no allocations) ----
__device__ uint2 g_h16[NND * 32];   // h / x0 per layer (fp16, row = 256B)
__device__ uint2 g_za [NND * 32];   // ping (fp16, scaled state s_k)
__device__ uint2 g_zb [NND * 32];   // pong
__device__ EdgeP g_ep[NE];          // CSR payload {src, w}
__device__ int   g_rowptr[NND + 1];
__device__ int   g_cur[NND];
__device__ int   g_bsum[128];
__device__ int   g_is64;
// persistent-prop state (reset by zero_detect_k every launch/replay)
__device__ int      g_work[40];     // per-step work-stealing counters
__device__ unsigned g_bar_cnt;
__device__ volatile unsigned g_bar_gen;

// ---- host-side stream/event for graph-forked CSR/encoder overlap ----
struct StreamInit {
    cudaStream_t s;
    cudaEvent_t  e1, e2;
    StreamInit() {
        cudaStreamCreateWithFlags(&s, cudaStreamNonBlocking);
        cudaEventCreateWithFlags(&e1, cudaEventDisableTiming);
        cudaEventCreateWithFlags(&e2, cudaEventDisableTiming);
    }
};
static StreamInit g_si;

__device__ __forceinline__ float gelu_f(float v) {
    return 0.5f * v * (1.0f + erff(v * 0.70710678118654752f));
}

__device__ __forceinline__ void fma16u(float4& acc, uint2 u, float wt) {
    __half2 a = *(__half2*)&u.x;
    __half2 b = *(__half2*)&u.y;
    float2 fa = __half22float2(a), fb = __half22float2(b);
    acc.x += wt * fa.x; acc.y += wt * fa.y;
    acc.z += wt * fb.x; acc.w += wt * fb.y;
}

__device__ __forceinline__ float4 ld16n(const uint2* __restrict__ z, int row, int lane) {
    uint2 u = z[row * 32 + lane];
    __half2 a = *(__half2*)&u.x;
    __half2 b = *(__half2*)&u.y;
    float2 fa = __half22float2(a), fb = __half22float2(b);
    return make_float4(fa.x, fa.y, fb.x, fb.y);
}

// ---------------- zero counters + dtype detect + persistent-state reset ----------------
__global__ void zero_detect_k(const int* __restrict__ ei32) {
    int i = blockIdx.x * blockDim.x + threadIdx.x;
    if (i < NND) g_cur[i] = 0;
    if (i < 40) g_work[i] = 0;
    if (i == 0) {
        int ok = 1;
        #pragma unroll
        for (int j = 0; j < 16; j++) ok &= (ei32[2 * j + 1] == 0);
        g_is64 = ok;
        g_bar_cnt = 0;
        g_bar_gen = 0;
    }
}

// ---------------- CSR build ----------------
__global__ void hist_k(const void* __restrict__ ei) {
    int i = blockIdx.x * blockDim.x + threadIdx.x;
    if (i >= NE) return;
    int dst = g_is64 ? (int)((const long long*)ei)[NE + i]
                     : ((const int*)ei)[NE + i];
    atomicAdd(&g_cur[dst], 1);
}

__global__ void scan1_k() {
    int tid = threadIdx.x, lane = tid & 31, wid = tid >> 5;
    int g = blockIdx.x * 1024 + tid;
    int v = (g < NND) ? g_cur[g] : 0;
    int x = v;
    #pragma unroll
    for (int d = 1; d < 32; d <<= 1) {
        int t = __shfl_up_sync(0xffffffffu, x, d);
        if (lane >= d) x += t;
    }
    __shared__ int ws[32];
    if (lane == 31) ws[wid] = x;
    __syncthreads();
    if (wid == 0) {
        int y = ws[lane];
        #pragma unroll
        for (int d = 1; d < 32; d <<= 1) {
            int t = __shfl_up_sync(0xffffffffu, y, d);
            if (lane >= d) y += t;
        }
        ws[lane] = y;
    }
    __syncthreads();
    int off = wid ? ws[wid - 1] : 0;
    int incl = x + off;
    if (g < NND) g_rowptr[g] = incl - v;
    if (tid == 1023) g_bsum[blockIdx.x] = incl;
}

__global__ void scan2_k(int nb) {
    if (threadIdx.x == 0 && blockIdx.x == 0) {
        int run = 0;
        for (int i = 0; i < nb; i++) { int t = g_bsum[i]; g_bsum[i] = run; run += t; }
        g_rowptr[NND] = run;
    }
}

__global__ void scan3_k() {
    int i = blockIdx.x * blockDim.x + threadIdx.x;
    if (i < NND) {
        int v = g_rowptr[i] + g_bsum[i >> 10];
        g_rowptr[i] = v;
        g_cur[i]    = v;
    }
}

__global__ void fill_k(const void* __restrict__ ei, const float* __restrict__ ew) {
    int i = blockIdx.x * blockDim.x + threadIdx.x;
    if (i >= NE) return;
    int src, dst;
    if (g_is64) {
        src = (int)((const long long*)ei)[i];
        dst = (int)((const long long*)ei)[NE + i];
    } else {
        src = ((const int*)ei)[i];
        dst = ((const int*)ei)[NE + i];
    }
    int pos = atomicAdd(&g_cur[dst], 1);
    EdgeP p; p.src = src; p.w = ew[i];
    g_ep[pos] = p;
}

// ---------------- encoder: h16 = fp16(gelu(LN(x @ Wenc^T))) ----------------
__global__ void __launch_bounds__(128) encoder_k(
    const float* __restrict__ x, const float* __restrict__ W,
    const float* __restrict__ gamma, const float* __restrict__ beta)
{
    extern __shared__ __align__(16) float sm[];
    float* sW   = sm;                     // 128*132
    float* sx   = sW + 128 * 132;         // ENC_M*128
    float* ssum = sx + ENC_M * 128;       // ENC_M*4
    float* ssq  = ssum + ENC_M * 4;       // ENC_M*4

    const int tid = threadIdx.x, lane = tid & 31, wid = tid >> 5;
    for (int i = tid; i < HID * HID; i += 128) {
        int c = i >> 7, k = i & 127;
        sW[c * 132 + k] = W[i];
    }
    const float gm = gamma[tid], bt = beta[tid];
    __half* h16 = (__half*)g_h16;
    __syncthreads();

    for (int base = blockIdx.x * ENC_M; base < NND; base += gridDim.x * ENC_M) {
        #pragma unroll
        for (int m = 0; m < ENC_M; m++) {
            int n = base + m;
            sx[m * 128 + tid] = (n < NND) ? x[n * 128 + tid] : 0.f;
        }
        __syncthreads();

        float acc[ENC_M];
        #pragma unroll
        for (int m = 0; m < ENC_M; m++) acc[m] = 0.f;
        #pragma unroll 2
        for (int k = 0; k < 128; k += 4) {
            float4 w4 = *(const float4*)(sW + tid * 132 + k);
            #pragma unroll
            for (int m = 0; m < ENC_M; m++) {
                float4 xv = *(const float4*)(sx + m * 128 + k);
                acc[m] += w4.x * xv.x + w4.y * xv.y + w4.z * xv.z + w4.w * xv.w;
            }
        }

        #pragma unroll
        for (int m = 0; m < ENC_M; m++) {
            float s = acc[m], q = acc[m] * acc[m];
            #pragma unroll
            for (int o = 16; o; o >>= 1) {
                s += __shfl_xor_sync(0xffffffffu, s, o);
                q += __shfl_xor_sync(0xffffffffu, q, o);
            }
            if (lane == 0) { ssum[m * 4 + wid] = s; ssq[m * 4 + wid] = q; }
        }
        __syncthreads();
        #pragma unroll
        for (int m = 0; m < ENC_M; m++) {
            float S = ssum[m * 4] + ssum[m * 4 + 1] + ssum[m * 4 + 2] + ssum[m * 4 + 3];
            float Q = ssq [m * 4] + ssq [m * 4 + 1] + ssq [m * 4 + 2] + ssq [m * 4 + 3];
            float mu  = S * (1.f / 128.f);
            float var = Q * (1.f / 128.f) - mu * mu;
            float inv = rsqrtf(var + 1e-5f);
            float v = gm * (acc[m] - mu) * inv + bt;
            v = gelu_f(v);
            int n = base + m;
            if (n < NND) h16[n * 128 + tid] = __float2half_rn(v);
        }
        __syncthreads();
    }
}

// ---------------- software grid barrier (all blocks resident) ----------------
__device__ __forceinline__ void grid_bar(unsigned gen_target) {
    __syncthreads();
    if (threadIdx.x == 0) {
        __threadfence();
        unsigned t = atomicAdd(&g_bar_cnt, 1);
        if (t == gridDim.x - 1) {
            g_bar_cnt = 0;
            __threadfence();
            g_bar_gen = gen_target;
        } else {
            while (g_bar_gen < gen_target) __nanosleep(128);
        }
        __threadfence();
    }
    __syncthreads();
}

// ---------------- persistent propagation with block-level work stealing ----------------
__global__ void __launch_bounds__(256) prop_persist_k(
    const float4* __restrict__ gamma4, const float4* __restrict__ beta4)
{
    const int lane = threadIdx.x & 31;
    const int wip  = threadIdx.x >> 5;   // warp in block (0..7)
    const float cA = 0.9f / 8.0f;
    __shared__ int sbase;

    uint2* h  = g_h16;
    uint2* za = g_za;
    uint2* zb = g_zb;

    unsigned gen = 0;
    for (int s = 0; s < 40; s++) {
        const int k = s - (s / 10) * 10;
        const uint2* zin  = (k == 0) ? h : ((k & 1) ? za : zb);
        uint2*       zout = (k == 9) ? h : ((k & 1) ? zb : za);
        const float cX = ldexpf(0.1f, -3 * (k + 1));
        const int fuse = (k == 9);

        for (;;) {
            __syncthreads();
            if (threadIdx.x == 0) sbase = atomicAdd(&g_work[s], CHUNK);
            __syncthreads();
            const int base = sbase;
            if (base >= NND) break;

            for (int j = 0; j < 8; j++) {
                const int w = base + wip * 8 + j;
                if (w >= NND) break;
                int beg = g_rowptr[w], end = g_rowptr[w + 1];

                float4 acc = make_float4(0.f, 0.f, 0.f, 0.f);
                int e = beg;
                for (; e + 8 <= end; e += 8) {
                    EdgeP p0 = g_ep[e],     p1 = g_ep[e + 1], p2 = g_ep[e + 2], p3 = g_ep[e + 3];
                    EdgeP p4 = g_ep[e + 4], p5 = g_ep[e + 5], p6 = g_ep[e + 6], p7 = g_ep[e + 7];
                    uint2 u0 = __ldcg(&zin[p0.src * 32 + lane]);
                    uint2 u1 = __ldcg(&zin[p1.src * 32 + lane]);
                    uint2 u2 = __ldcg(&zin[p2.src * 32 + lane]);
                    uint2 u3 = __ldcg(&zin[p3.src * 32 + lane]);
                    uint2 u4 = __ldcg(&zin[p4.src * 32 + lane]);
                    uint2 u5 = __ldcg(&zin[p5.src * 32 + lane]);
                    uint2 u6 = __ldcg(&zin[p6.src * 32 + lane]);
                    uint2 u7 = __ldcg(&zin[p7.src * 32 + lane]);
                    fma16u(acc, u0, p0.w); fma16u(acc, u1, p1.w);
                    fma16u(acc, u2, p2.w); fma16u(acc, u3, p3.w);
                    fma16u(acc, u4, p4.w); fma16u(acc, u5, p5.w);
                    fma16u(acc, u6, p6.w); fma16u(acc, u7, p7.w);
                }
                if (e + 4 <= end) {
                    EdgeP p0 = g_ep[e], p1 = g_ep[e + 1], p2 = g_ep[e + 2], p3 = g_ep[e + 3];
                    uint2 u0 = __ldcg(&zin[p0.src * 32 + lane]);
                    uint2 u1 = __ldcg(&zin[p1.src * 32 + lane]);
                    uint2 u2 = __ldcg(&zin[p2.src * 32 + lane]);
                    uint2 u3 = __ldcg(&zin[p3.src * 32 + lane]);
                    fma16u(acc, u0, p0.w); fma16u(acc, u1, p1.w);
                    fma16u(acc, u2, p2.w); fma16u(acc, u3, p3.w);
                    e += 4;
                }
                for (; e < end; e++) {
                    EdgeP p = g_ep[e];
                    uint2 u = __ldcg(&zin[p.src * 32 + lane]);
                    fma16u(acc, u, p.w);
                }

                uint2 xu = __ldcg(&h[w * 32 + lane]);
                float4 xv;
                {
                    __half2 a = *(__half2*)&xu.x;
                    __half2 b = *(__half2*)&xu.y;
                    float2 fa = __half22float2(a), fb = __half22float2(b);
                    xv = make_float4(fa.x, fa.y, fb.x, fb.y);
                }

                float4 r;
                r.x = cA * acc.x + cX * xv.x;
                r.y = cA * acc.y + cX * xv.y;
                r.z = cA * acc.z + cX * xv.z;
                r.w = cA * acc.w + cX * xv.w;

                if (fuse) {
                    const float FS = 1073741824.0f;   // 8^10 = 2^30, exact
                    r.x = gelu_f(r.x * FS); r.y = gelu_f(r.y * FS);
                    r.z = gelu_f(r.z * FS); r.w = gelu_f(r.w * FS);
                    float sum = r.x + r.y + r.z + r.w;
                    #pragma unroll
                    for (int off = 16; off; off >>= 1)
                        sum += __shfl_xor_sync(0xffffffffu, sum, off);
                    float mu = sum * (1.f / 128.f);
                    float dx = r.x - mu, dy = r.y - mu, dz = r.z - mu, dw = r.w - mu;
                    float q = dx * dx + dy * dy + dz * dz + dw * dw;
                    #pragma unroll
                    for (int off = 16; off; off >>= 1)
                        q += __shfl_xor_sync(0xffffffffu, q, off);
                    float var = q * (1.f / 128.f);
                    float inv = rsqrtf(var + 1e-5f);
                    float4 gmv = gamma4[lane], btv = beta4[lane];
                    r.x = gmv.x * dx * inv + btv.x;
                    r.y = gmv.y * dy * inv + btv.y;
                    r.z = gmv.z * dz * inv + btv.z;
                    r.w = gmv.w * dw * inv + btv.w;
                }

                __half2 o0 = __floats2half2_rn(r.x, r.y);
                __half2 o1 = __floats2half2_rn(r.z, r.w);
                uint2 ou;
                ou.x = *(unsigned*)&o0;
                ou.y = *(unsigned*)&o1;
                __stcg(&zout[w * 32 + lane], ou);
            }
        }

        gen++;
        if (s != 39) grid_bar(gen);
    }
}

// ---------------- decoder: out = h16 @ Wdec^T ----------------
__global__ void __launch_bounds__(256) decoder_k(
    const float* __restrict__ Wd, float* __restrict__ out)
{
    __shared__ __align__(16) float sW[OUTC * 132];
    __shared__ __align__(16) float sx[4 * 128];
    const int tid = threadIdx.x;
    for (int i = tid; i < OUTC * HID; i += 256) {
        int c = i >> 7, k = i & 127;
        sW[c * 132 + k] = Wd[i];
    }
    __syncthreads();
    const int sub = tid >> 6, c = tid & 63;

    for (int base = blockIdx.x * 4; base < NND; base += gridDim.x * 4) {
        if (tid < 128) {
            int m = tid >> 5, ll = tid & 31;
            int n = base + m;
            float4 v = (n < NND) ? ld16n(g_h16, n, ll)
                                 : make_float4(0.f, 0.f, 0.f, 0.f);
            *(float4*)(sx + m * 128 + ll * 4) = v;
        }
        __syncthreads();
        float acc = 0.f;
        #pragma unroll 4
        for (int k = 0; k < 128; k += 4) {
            float4 w4 = *(const float4*)(sW + c * 132 + k);
            float4 xv = *(const float4*)(sx + sub * 128 + k);
            acc += w4.x * xv.x + w4.y * xv.y + w4.z * xv.z + w4.w * xv.w;
        }
        int n = base + sub;
        if (n < NND) out[n * 64 + c] = acc;
        __syncthreads();
    }
}

// ---------------- launch ----------------
extern "C" void kernel_launch(void* const* d_in, const int* in_sizes, int n_in,
                              void* d_out, int out_size)
{
    const float* x     = (const float*)d_in[0];
    const void*  ei    = (const void*) d_in[1];
    const float* ew    = (const float*)d_in[2];
    const float* Wenc  = (const float*)d_in[3];
    const float* Wdec  = (const float*)d_in[4];
    const float* gamma = (const float*)d_in[5];
    const float* beta  = (const float*)d_in[6];
    float* out = (float*)d_out;

    const int NB_SCAN = (NND + 1023) / 1024;   // 98

    // ---- fork: CSR build on side stream, encoder on main stream ----
    cudaEventRecord(g_si.e1, 0);
    cudaStreamWaitEvent(g_si.s, g_si.e1, 0);

    zero_detect_k<<<(NND + 255) / 256, 256, 0, g_si.s>>>((const int*)ei);
    hist_k<<<(NE + 255) / 256, 256, 0, g_si.s>>>(ei);
    scan1_k<<<NB_SCAN, 1024, 0, g_si.s>>>();
    scan2_k<<<1, 32, 0, g_si.s>>>(NB_SCAN);
    scan3_k<<<(NND + 255) / 256, 256, 0, g_si.s>>>();
    fill_k<<<(NE + 255) / 256, 256, 0, g_si.s>>>(ei, ew);
    cudaEventRecord(g_si.e2, g_si.s);

    int enc_smem = (128 * 132 + ENC_M * 128 + ENC_M * 8) * (int)sizeof(float);
    cudaFuncSetAttribute(encoder_k, cudaFuncAttributeMaxDynamicSharedMemorySize, enc_smem);
    encoder_k<<<444, 128, enc_smem>>>(x, Wenc, gamma, beta);

    // ---- join: propagation needs both CSR and encoder output ----
    cudaStreamWaitEvent(0, g_si.e2, 0);

    const float4* g4 = (const float4*)gamma;
    const float4* b4 = (const float4*)beta;

    // persistent grid: guaranteed-resident block count
    int dev = 0;
    cudaGetDevice(&dev);
    int sms = 0;
    cudaDeviceGetAttribute(&sms, cudaDevAttrMultiProcessorCount, dev);
    int bpm = 0;
    cudaOccupancyMaxActiveBlocksPerMultiprocessor(&bpm, prop_persist_k, 256, 0);
    if (bpm < 1) bpm = 1;
    int pgrid = sms * bpm;
    if (pgrid > 1563) pgrid = 1563;   // no more blocks than chunks

    prop_persist_k<<<pgrid, 256>>>(g4, b4);

    decoder_k<<<888, 256>>>(Wdec, out);
}

// round 15
// speedup vs baseline: 1.3241x; 1.3241x over previous
#include <cuda_runtime.h>
#include <cuda_fp16.h>
#include <math.h>

#define NND 100000
#define NE  1600000
#define HID 128
#define OUTC 64
#define ENC_M 8

struct __align__(8) EdgeP { int src; float w; };

// ---- scratch (static device globals; no allocations) ----
__device__ uint2 g_h16[NND * 32];   // h / x0 per layer (fp16, row = 256B)
__device__ uint2 g_za [NND * 32];   // ping (fp16, scaled state s_k)
__device__ uint2 g_zb [NND * 32];   // pong
__device__ EdgeP g_ep[NE];          // CSR payload {src, w}
__device__ int   g_rowptr[NND + 1];
__device__ int   g_cur[NND];
__device__ int   g_bsum[128];
__device__ int   g_is64;

// ---- host-side stream/event for graph-forked CSR/encoder overlap ----
struct StreamInit {
    cudaStream_t s;
    cudaEvent_t  e1, e2;
    StreamInit() {
        cudaStreamCreateWithFlags(&s, cudaStreamNonBlocking);
        cudaEventCreateWithFlags(&e1, cudaEventDisableTiming);
        cudaEventCreateWithFlags(&e2, cudaEventDisableTiming);
    }
};
static StreamInit g_si;

__device__ __forceinline__ float gelu_f(float v) {
    return 0.5f * v * (1.0f + erff(v * 0.70710678118654752f));
}

__device__ __forceinline__ float4 ld16(const uint2* __restrict__ z, int row, int lane) {
    uint2 u = z[row * 32 + lane];
    __half2 a = *(__half2*)&u.x;
    __half2 b = *(__half2*)&u.y;
    float2 fa = __half22float2(a), fb = __half22float2(b);
    return make_float4(fa.x, fa.y, fb.x, fb.y);
}

__device__ __forceinline__ void st16(uint2* __restrict__ z, int row, int lane, float4 v) {
    __half2 a = __floats2half2_rn(v.x, v.y);
    __half2 b = __floats2half2_rn(v.z, v.w);
    uint2 u;
    u.x = *(unsigned*)&a;
    u.y = *(unsigned*)&b;
    z[row * 32 + lane] = u;
}

__device__ __forceinline__ void fma16(float4& acc, uint2 u, float wt) {
    __half2 a = *(__half2*)&u.x;
    __half2 b = *(__half2*)&u.y;
    float2 fa = __half22float2(a), fb = __half22float2(b);
    acc.x += wt * fa.x; acc.y += wt * fa.y;
    acc.z += wt * fb.x; acc.w += wt * fb.y;
}

// ---------------- zero counters + dtype detect (merged) ----------------
__global__ void zero_detect_k(const int* __restrict__ ei32) {
    int i = blockIdx.x * blockDim.x + threadIdx.x;
    if (i < NND) g_cur[i] = 0;
    if (i == 0) {
        int ok = 1;
        #pragma unroll
        for (int j = 0; j < 16; j++) ok &= (ei32[2 * j + 1] == 0);
        g_is64 = ok;
    }
}

// ---------------- CSR build ----------------
__global__ void hist_k(const void* __restrict__ ei) {
    int i = blockIdx.x * blockDim.x + threadIdx.x;
    if (i >= NE) return;
    int dst = g_is64 ? (int)((const long long*)ei)[NE + i]
                     : ((const int*)ei)[NE + i];
    atomicAdd(&g_cur[dst], 1);
}

__global__ void scan1_k() {
    int tid = threadIdx.x, lane = tid & 31, wid = tid >> 5;
    int g = blockIdx.x * 1024 + tid;
    int v = (g < NND) ? g_cur[g] : 0;
    int x = v;
    #pragma unroll
    for (int d = 1; d < 32; d <<= 1) {
        int t = __shfl_up_sync(0xffffffffu, x, d);
        if (lane >= d) x += t;
    }
    __shared__ int ws[32];
    if (lane == 31) ws[wid] = x;
    __syncthreads();
    if (wid == 0) {
        int y = ws[lane];
        #pragma unroll
        for (int d = 1; d < 32; d <<= 1) {
            int t = __shfl_up_sync(0xffffffffu, y, d);
            if (lane >= d) y += t;
        }
        ws[lane] = y;
    }
    __syncthreads();
    int off = wid ? ws[wid - 1] : 0;
    int incl = x + off;
    if (g < NND) g_rowptr[g] = incl - v;
    if (tid == 1023) g_bsum[blockIdx.x] = incl;
}

__global__ void scan2_k(int nb) {
    if (threadIdx.x == 0 && blockIdx.x == 0) {
        int run = 0;
        for (int i = 0; i < nb; i++) { int t = g_bsum[i]; g_bsum[i] = run; run += t; }
        g_rowptr[NND] = run;
    }
}

__global__ void scan3_k() {
    int i = blockIdx.x * blockDim.x + threadIdx.x;
    if (i < NND) {
        int v = g_rowptr[i] + g_bsum[i >> 10];
        g_rowptr[i] = v;
        g_cur[i]    = v;
    }
}

__global__ void fill_k(const void* __restrict__ ei, const float* __restrict__ ew) {
    int i = blockIdx.x * blockDim.x + threadIdx.x;
    if (i >= NE) return;
    int src, dst;
    if (g_is64) {
        src = (int)((const long long*)ei)[i];
        dst = (int)((const long long*)ei)[NE + i];
    } else {
        src = ((const int*)ei)[i];
        dst = ((const int*)ei)[NE + i];
    }
    int pos = atomicAdd(&g_cur[dst], 1);
    EdgeP p; p.src = src; p.w = ew[i];
    g_ep[pos] = p;
}

// ---------------- encoder: h16 = fp16(gelu(LN(x @ Wenc^T))) ----------------
__global__ void __launch_bounds__(128) encoder_k(
    const float* __restrict__ x, const float* __restrict__ W,
    const float* __restrict__ gamma, const float* __restrict__ beta)
{
    extern __shared__ __align__(16) float sm[];
    float* sW   = sm;                     // 128*132
    float* sx   = sW + 128 * 132;         // ENC_M*128
    float* ssum = sx + ENC_M * 128;       // ENC_M*4
    float* ssq  = ssum + ENC_M * 4;       // ENC_M*4

    const int tid = threadIdx.x, lane = tid & 31, wid = tid >> 5;
    for (int i = tid; i < HID * HID; i += 128) {
        int c = i >> 7, k = i & 127;
        sW[c * 132 + k] = W[i];
    }
    const float gm = gamma[tid], bt = beta[tid];
    __half* h16 = (__half*)g_h16;
    __syncthreads();

    for (int base = blockIdx.x * ENC_M; base < NND; base += gridDim.x * ENC_M) {
        #pragma unroll
        for (int m = 0; m < ENC_M; m++) {
            int n = base + m;
            sx[m * 128 + tid] = (n < NND) ? x[n * 128 + tid] : 0.f;
        }
        __syncthreads();

        float acc[ENC_M];
        #pragma unroll
        for (int m = 0; m < ENC_M; m++) acc[m] = 0.f;
        #pragma unroll 2
        for (int k = 0; k < 128; k += 4) {
            float4 w4 = *(const float4*)(sW + tid * 132 + k);
            #pragma unroll
            for (int m = 0; m < ENC_M; m++) {
                float4 xv = *(const float4*)(sx + m * 128 + k);
                acc[m] += w4.x * xv.x + w4.y * xv.y + w4.z * xv.z + w4.w * xv.w;
            }
        }

        #pragma unroll
        for (int m = 0; m < ENC_M; m++) {
            float s = acc[m], q = acc[m] * acc[m];
            #pragma unroll
            for (int o = 16; o; o >>= 1) {
                s += __shfl_xor_sync(0xffffffffu, s, o);
                q += __shfl_xor_sync(0xffffffffu, q, o);
            }
            if (lane == 0) { ssum[m * 4 + wid] = s; ssq[m * 4 + wid] = q; }
        }
        __syncthreads();
        #pragma unroll
        for (int m = 0; m < ENC_M; m++) {
            float S = ssum[m * 4] + ssum[m * 4 + 1] + ssum[m * 4 + 2] + ssum[m * 4 + 3];
            float Q = ssq [m * 4] + ssq [m * 4 + 1] + ssq [m * 4 + 2] + ssq [m * 4 + 3];
            float mu  = S * (1.f / 128.f);
            float var = Q * (1.f / 128.f) - mu * mu;
            float inv = rsqrtf(var + 1e-5f);
            float v = gm * (acc[m] - mu) * inv + bt;
            v = gelu_f(v);
            int n = base + m;
            if (n < NND) h16[n * 128 + tid] = __float2half_rn(v);
        }
        __syncthreads();
    }
}

// ---------------- propagation step (warp per node, fp16 scaled state) ----------------
__global__ void __launch_bounds__(256) prop16_k(
    const uint2* __restrict__ z, const uint2* __restrict__ x0, uint2* __restrict__ o,
    const float4* __restrict__ gamma4, const float4* __restrict__ beta4,
    float cA, float cX, int fuse)
{
    int w = (blockIdx.x * blockDim.x + threadIdx.x) >> 5;
    int lane = threadIdx.x & 31;
    if (w >= NND) return;
    int beg = g_rowptr[w], end = g_rowptr[w + 1];

    float4 acc = make_float4(0.f, 0.f, 0.f, 0.f);
    int e = beg;
    for (; e + 8 <= end; e += 8) {
        EdgeP p0 = g_ep[e],     p1 = g_ep[e + 1], p2 = g_ep[e + 2], p3 = g_ep[e + 3];
        EdgeP p4 = g_ep[e + 4], p5 = g_ep[e + 5], p6 = g_ep[e + 6], p7 = g_ep[e + 7];
        uint2 u0 = z[p0.src * 32 + lane];
        uint2 u1 = z[p1.src * 32 + lane];
        uint2 u2 = z[p2.src * 32 + lane];
        uint2 u3 = z[p3.src * 32 + lane];
        uint2 u4 = z[p4.src * 32 + lane];
        uint2 u5 = z[p5.src * 32 + lane];
        uint2 u6 = z[p6.src * 32 + lane];
        uint2 u7 = z[p7.src * 32 + lane];
        fma16(acc, u0, p0.w); fma16(acc, u1, p1.w);
        fma16(acc, u2, p2.w); fma16(acc, u3, p3.w);
        fma16(acc, u4, p4.w); fma16(acc, u5, p5.w);
        fma16(acc, u6, p6.w); fma16(acc, u7, p7.w);
    }
    if (e + 4 <= end) {
        EdgeP p0 = g_ep[e], p1 = g_ep[e + 1], p2 = g_ep[e + 2], p3 = g_ep[e + 3];
        uint2 u0 = z[p0.src * 32 + lane];
        uint2 u1 = z[p1.src * 32 + lane];
        uint2 u2 = z[p2.src * 32 + lane];
        uint2 u3 = z[p3.src * 32 + lane];
        fma16(acc, u0, p0.w); fma16(acc, u1, p1.w);
        fma16(acc, u2, p2.w); fma16(acc, u3, p3.w);
        e += 4;
    }
    for (; e < end; e++) {
        EdgeP p = g_ep[e];
        uint2 u = z[p.src * 32 + lane];
        fma16(acc, u, p.w);
    }

    float4 xv = ld16(x0, w, lane);
    float4 r;
    r.x = cA * acc.x + cX * xv.x;
    r.y = cA * acc.y + cX * xv.y;
    r.z = cA * acc.z + cX * xv.z;
    r.w = cA * acc.w + cX * xv.w;

    if (fuse) {
        const float FS = 1073741824.0f;   // 8^10 = 2^30, exact
        r.x = gelu_f(r.x * FS); r.y = gelu_f(r.y * FS);
        r.z = gelu_f(r.z * FS); r.w = gelu_f(r.w * FS);
        float s = r.x + r.y + r.z + r.w;
        #pragma unroll
        for (int off = 16; off; off >>= 1)
            s += __shfl_xor_sync(0xffffffffu, s, off);
        float mu = s * (1.f / 128.f);
        float dx = r.x - mu, dy = r.y - mu, dz = r.z - mu, dw = r.w - mu;
        float q = dx * dx + dy * dy + dz * dz + dw * dw;
        #pragma unroll
        for (int off = 16; off; off >>= 1)
            q += __shfl_xor_sync(0xffffffffu, q, off);
        float var = q * (1.f / 128.f);
        float inv = rsqrtf(var + 1e-5f);
        float4 gmv = gamma4[lane], btv = beta4[lane];
        r.x = gmv.x * dx * inv + btv.x;
        r.y = gmv.y * dy * inv + btv.y;
        r.z = gmv.z * dz * inv + btv.z;
        r.w = gmv.w * dw * inv + btv.w;
    }
    st16(o, w, lane, r);
}

// ---------------- decoder: out = h16 @ Wdec^T ----------------
__global__ void __launch_bounds__(256) decoder_k(
    const float* __restrict__ Wd, float* __restrict__ out)
{
    __shared__ __align__(16) float sW[OUTC * 132];
    __shared__ __align__(16) float sx[4 * 128];
    const int tid = threadIdx.x;
    for (int i = tid; i < OUTC * HID; i += 256) {
        int c = i >> 7, k = i & 127;
        sW[c * 132 + k] = Wd[i];
    }
    __syncthreads();
    const int sub = tid >> 6, c = tid & 63;

    for (int base = blockIdx.x * 4; base < NND; base += gridDim.x * 4) {
        if (tid < 128) {
            int m = tid >> 5, ll = tid & 31;
            int n = base + m;
            float4 v = (n < NND) ? ld16(g_h16, n, ll)
                                 : make_float4(0.f, 0.f, 0.f, 0.f);
            *(float4*)(sx + m * 128 + ll * 4) = v;
        }
        __syncthreads();
        float acc = 0.f;
        #pragma unroll 4
        for (int k = 0; k < 128; k += 4) {
            float4 w4 = *(const float4*)(sW + c * 132 + k);
            float4 xv = *(const float4*)(sx + sub * 128 + k);
            acc += w4.x * xv.x + w4.y * xv.y + w4.z * xv.z + w4.w * xv.w;
        }
        int n = base + sub;
        if (n < NND) out[n * 64 + c] = acc;
        __syncthreads();
    }
}

// ---------------- launch ----------------
extern "C" void kernel_launch(void* const* d_in, const int* in_sizes, int n_in,
                              void* d_out, int out_size)
{
    const float* x     = (const float*)d_in[0];
    const void*  ei    = (const void*) d_in[1];
    const float* ew    = (const float*)d_in[2];
    const float* Wenc  = (const float*)d_in[3];
    const float* Wdec  = (const float*)d_in[4];
    const float* gamma = (const float*)d_in[5];
    const float* beta  = (const float*)d_in[6];
    float* out = (float*)d_out;

    void *ph, *pza, *pzb;
    cudaGetSymbolAddress(&ph,  g_h16);
    cudaGetSymbolAddress(&pza, g_za);
    cudaGetSymbolAddress(&pzb, g_zb);
    uint2* h16 = (uint2*)ph;
    uint2* za  = (uint2*)pza;
    uint2* zb  = (uint2*)pzb;

    const int NB_SCAN = (NND + 1023) / 1024;   // 98

    // ---- fork: CSR build on side stream, encoder on main stream ----
    cudaEventRecord(g_si.e1, 0);
    cudaStreamWaitEvent(g_si.s, g_si.e1, 0);

    zero_detect_k<<<(NND + 255) / 256, 256, 0, g_si.s>>>((const int*)ei);
    hist_k<<<(NE + 255) / 256, 256, 0, g_si.s>>>(ei);
    scan1_k<<<NB_SCAN, 1024, 0, g_si.s>>>();
    scan2_k<<<1, 32, 0, g_si.s>>>(NB_SCAN);
    scan3_k<<<(NND + 255) / 256, 256, 0, g_si.s>>>();
    fill_k<<<(NE + 255) / 256, 256, 0, g_si.s>>>(ei, ew);
    cudaEventRecord(g_si.e2, g_si.s);

    int enc_smem = (128 * 132 + ENC_M * 128 + ENC_M * 8) * (int)sizeof(float);
    cudaFuncSetAttribute(encoder_k, cudaFuncAttributeMaxDynamicSharedMemorySize, enc_smem);
    encoder_k<<<444, 128, enc_smem>>>(x, Wenc, gamma, beta);

    // ---- join: prop needs both CSR and encoder output ----
    cudaStreamWaitEvent(0, g_si.e2, 0);

    const float4* g4 = (const float4*)gamma;
    const float4* b4 = (const float4*)beta;
    const int pblocks = (NND * 32) / 256;      // 12500

    const float cA = 0.9f / 8.0f;
    float cX[10];
    {
        float p = 1.0f;
        for (int k = 0; k < 10; k++) { p *= 0.125f; cX[k] = 0.1f * p; }
    }

    for (int layer = 0; layer < 4; layer++) {
        prop16_k<<<pblocks, 256>>>(h16, h16, za, g4, b4, cA, cX[0], 0);
        for (int k = 1; k < 9; k++) {
            const uint2* in = (k & 1) ? za : zb;
            uint2*       o  = (k & 1) ? zb : za;
            prop16_k<<<pblocks, 256>>>(in, h16, o, g4, b4, cA, cX[k], 0);
        }
        prop16_k<<<pblocks, 256>>>(za, h16, h16, g4, b4, cA, cX[9], 1);
    }

    decoder_k<<<888, 256>>>(Wdec, out);
}

// round 16
// speedup vs baseline: 1.4306x; 1.0804x over previous
#include <cuda_runtime.h>
#include <cuda_fp16.h>
#include <mma.h>
#include <math.h>

using namespace nvcuda;

#define NND 100000
#define NE  1600000
#define HID 128
#define OUTC 64
#define ENC_M 8
#define NTILE 781           // full 128-row tiles; tail = 32 nodes
#define TAIL_START (NTILE * 128)

struct __align__(8) EdgeP { int src; float w; };

// ---- scratch (static device globals; no allocations) ----
__device__ uint2 g_h16[NND * 32];   // h / x0 per layer (fp16, row = 256B)
__device__ uint2 g_za [NND * 32];   // ping (fp16, scaled state s_k)
__device__ uint2 g_zb [NND * 32];   // pong
__device__ EdgeP g_ep[NE];          // CSR payload {src, w}
__device__ int   g_rowptr[NND + 1];
__device__ int   g_cur[NND];
__device__ int   g_bsum[128];
__device__ int   g_is64;

// ---- host-side stream/event for graph-forked CSR/encoder overlap ----
struct StreamInit {
    cudaStream_t s;
    cudaEvent_t  e1, e2;
    StreamInit() {
        cudaStreamCreateWithFlags(&s, cudaStreamNonBlocking);
        cudaEventCreateWithFlags(&e1, cudaEventDisableTiming);
        cudaEventCreateWithFlags(&e2, cudaEventDisableTiming);
    }
};
static StreamInit g_si;

__device__ __forceinline__ float gelu_f(float v) {
    return 0.5f * v * (1.0f + erff(v * 0.70710678118654752f));
}

__device__ __forceinline__ float4 ld16(const uint2* __restrict__ z, int row, int lane) {
    uint2 u = z[row * 32 + lane];
    __half2 a = *(__half2*)&u.x;
    __half2 b = *(__half2*)&u.y;
    float2 fa = __half22float2(a), fb = __half22float2(b);
    return make_float4(fa.x, fa.y, fb.x, fb.y);
}

__device__ __forceinline__ void st16(uint2* __restrict__ z, int row, int lane, float4 v) {
    __half2 a = __floats2half2_rn(v.x, v.y);
    __half2 b = __floats2half2_rn(v.z, v.w);
    uint2 u;
    u.x = *(unsigned*)&a;
    u.y = *(unsigned*)&b;
    z[row * 32 + lane] = u;
}

__device__ __forceinline__ void fma16(float4& acc, uint2 u, float wt) {
    __half2 a = *(__half2*)&u.x;
    __half2 b = *(__half2*)&u.y;
    float2 fa = __half22float2(a), fb = __half22float2(b);
    acc.x += wt * fa.x; acc.y += wt * fa.y;
    acc.z += wt * fb.x; acc.w += wt * fb.y;
}

// ---------------- zero counters + dtype detect (merged) ----------------
__global__ void zero_detect_k(const int* __restrict__ ei32) {
    int i = blockIdx.x * blockDim.x + threadIdx.x;
    if (i < NND) g_cur[i] = 0;
    if (i == 0) {
        int ok = 1;
        #pragma unroll
        for (int j = 0; j < 16; j++) ok &= (ei32[2 * j + 1] == 0);
        g_is64 = ok;
    }
}

// ---------------- CSR build ----------------
__global__ void hist_k(const void* __restrict__ ei) {
    int i = blockIdx.x * blockDim.x + threadIdx.x;
    if (i >= NE) return;
    int dst = g_is64 ? (int)((const long long*)ei)[NE + i]
                     : ((const int*)ei)[NE + i];
    atomicAdd(&g_cur[dst], 1);
}

__global__ void scan1_k() {
    int tid = threadIdx.x, lane = tid & 31, wid = tid >> 5;
    int g = blockIdx.x * 1024 + tid;
    int v = (g < NND) ? g_cur[g] : 0;
    int x = v;
    #pragma unroll
    for (int d = 1; d < 32; d <<= 1) {
        int t = __shfl_up_sync(0xffffffffu, x, d);
        if (lane >= d) x += t;
    }
    __shared__ int ws[32];
    if (lane == 31) ws[wid] = x;
    __syncthreads();
    if (wid == 0) {
        int y = ws[lane];
        #pragma unroll
        for (int d = 1; d < 32; d <<= 1) {
            int t = __shfl_up_sync(0xffffffffu, y, d);
            if (lane >= d) y += t;
        }
        ws[lane] = y;
    }
    __syncthreads();
    int off = wid ? ws[wid - 1] : 0;
    int incl = x + off;
    if (g < NND) g_rowptr[g] = incl - v;
    if (tid == 1023) g_bsum[blockIdx.x] = incl;
}

__global__ void scan2_k(int nb) {
    if (threadIdx.x == 0 && blockIdx.x == 0) {
        int run = 0;
        for (int i = 0; i < nb; i++) { int t = g_bsum[i]; g_bsum[i] = run; run += t; }
        g_rowptr[NND] = run;
    }
}

__global__ void scan3_k() {
    int i = blockIdx.x * blockDim.x + threadIdx.x;
    if (i < NND) {
        int v = g_rowptr[i] + g_bsum[i >> 10];
        g_rowptr[i] = v;
        g_cur[i]    = v;
    }
}

__global__ void fill_k(const void* __restrict__ ei, const float* __restrict__ ew) {
    int i = blockIdx.x * blockDim.x + threadIdx.x;
    if (i >= NE) return;
    int src, dst;
    if (g_is64) {
        src = (int)((const long long*)ei)[i];
        dst = (int)((const long long*)ei)[NE + i];
    } else {
        src = ((const int*)ei)[i];
        dst = ((const int*)ei)[NE + i];
    }
    int pos = atomicAdd(&g_cur[dst], 1);
    EdgeP p; p.src = src; p.w = ew[i];
    g_ep[pos] = p;
}

// ---------------- encoder (wmma): h16 = fp16(gelu(LN(x @ Wenc^T))) ----------------
// 256 thr = 8 warps; tile 128 nodes x 128 cols. smem: W16 32KB | buf 64KB
// (buf holds x16 during mainloop, then C fp32 for the LN epilogue).
__global__ void __launch_bounds__(256) encoder_wmma_k(
    const float* __restrict__ x, const float* __restrict__ W,
    const float* __restrict__ gamma, const float* __restrict__ beta)
{
    extern __shared__ __align__(16) char sm[];
    __half* sW = (__half*)sm;                    // [128][128] row-major
    __half* sx = (__half*)(sm + 32768);          // [128][128] row-major (mainloop)
    float*  sC = (float*) (sm + 32768);          // [128][128] fp32 (epilogue, aliases sx)

    const int tid = threadIdx.x, wid = tid >> 5, lane = tid & 31;

    for (int i = tid; i < 128 * 128; i += 256) sW[i] = __float2half_rn(W[i]);
    __syncthreads();

    for (int tile = blockIdx.x; tile < NTILE; tile += gridDim.x) {
        const int row0 = tile * 128;
        for (int i = tid; i < 128 * 128; i += 256)
            sx[i] = __float2half_rn(x[row0 * 128 + i]);
        __syncthreads();

        wmma::fragment<wmma::accumulator, 16, 16, 16, float> acc[8];
        #pragma unroll
        for (int nf = 0; nf < 8; nf++) wmma::fill_fragment(acc[nf], 0.f);
        #pragma unroll
        for (int k0 = 0; k0 < 8; k0++) {
            wmma::fragment<wmma::matrix_a, 16, 16, 16, __half, wmma::row_major> a;
            wmma::load_matrix_sync(a, sx + (wid * 16) * 128 + k0 * 16, 128);
            #pragma unroll
            for (int nf = 0; nf < 8; nf++) {
                wmma::fragment<wmma::matrix_b, 16, 16, 16, __half, wmma::col_major> b;
                wmma::load_matrix_sync(b, sW + (nf * 16) * 128 + k0 * 16, 128);
                wmma::mma_sync(acc[nf], a, b, acc[nf]);
            }
        }
        __syncthreads();   // sx reads complete; sC may now overwrite
        #pragma unroll
        for (int nf = 0; nf < 8; nf++)
            wmma::store_matrix_sync(sC + (wid * 16) * 128 + nf * 16, acc[nf], 128,
                                    wmma::mem_row_major);
        __syncthreads();

        // LN + GELU per row (warp per row, 4 channels per lane), write h16
        for (int r = wid; r < 128; r += 8) {
            float4 v = *(float4*)(sC + r * 128 + lane * 4);
            float s = v.x + v.y + v.z + v.w;
            #pragma unroll
            for (int o = 16; o; o >>= 1) s += __shfl_xor_sync(0xffffffffu, s, o);
            float mu = s * (1.f / 128.f);
            float dx = v.x - mu, dy = v.y - mu, dz = v.z - mu, dw = v.w - mu;
            float q = dx * dx + dy * dy + dz * dz + dw * dw;
            #pragma unroll
            for (int o = 16; o; o >>= 1) q += __shfl_xor_sync(0xffffffffu, q, o);
            float inv = rsqrtf(q * (1.f / 128.f) + 1e-5f);
            float4 gm = *(const float4*)(gamma + lane * 4);
            float4 bt = *(const float4*)(beta  + lane * 4);
            float4 h;
            h.x = gelu_f(gm.x * dx * inv + bt.x);
            h.y = gelu_f(gm.y * dy * inv + bt.y);
            h.z = gelu_f(gm.z * dz * inv + bt.z);
            h.w = gelu_f(gm.w * dw * inv + bt.w);
            st16(g_h16, row0 + r, lane, h);
        }
        __syncthreads();
    }
}

// ---------------- scalar encoder (tail nodes) ----------------
__global__ void __launch_bounds__(128) encoder_k(
    const float* __restrict__ x, const float* __restrict__ W,
    const float* __restrict__ gamma, const float* __restrict__ beta, int start)
{
    extern __shared__ __align__(16) float smf[];
    float* sW   = smf;                    // 128*132
    float* sx   = sW + 128 * 132;         // ENC_M*128
    float* ssum = sx + ENC_M * 128;
    float* ssq  = ssum + ENC_M * 4;

    const int tid = threadIdx.x, lane = tid & 31, wid = tid >> 5;
    for (int i = tid; i < HID * HID; i += 128) {
        int c = i >> 7, k = i & 127;
        sW[c * 132 + k] = W[i];
    }
    const float gm = gamma[tid], bt = beta[tid];
    __half* h16 = (__half*)g_h16;
    __syncthreads();

    for (int base = start + blockIdx.x * ENC_M; base < NND; base += gridDim.x * ENC_M) {
        #pragma unroll
        for (int m = 0; m < ENC_M; m++) {
            int n = base + m;
            sx[m * 128 + tid] = (n < NND) ? x[n * 128 + tid] : 0.f;
        }
        __syncthreads();

        float acc[ENC_M];
        #pragma unroll
        for (int m = 0; m < ENC_M; m++) acc[m] = 0.f;
        #pragma unroll 2
        for (int k = 0; k < 128; k += 4) {
            float4 w4 = *(const float4*)(sW + tid * 132 + k);
            #pragma unroll
            for (int m = 0; m < ENC_M; m++) {
                float4 xv = *(const float4*)(sx + m * 128 + k);
                acc[m] += w4.x * xv.x + w4.y * xv.y + w4.z * xv.z + w4.w * xv.w;
            }
        }

        #pragma unroll
        for (int m = 0; m < ENC_M; m++) {
            float s = acc[m], q = acc[m] * acc[m];
            #pragma unroll
            for (int o = 16; o; o >>= 1) {
                s += __shfl_xor_sync(0xffffffffu, s, o);
                q += __shfl_xor_sync(0xffffffffu, q, o);
            }
            if (lane == 0) { ssum[m * 4 + wid] = s; ssq[m * 4 + wid] = q; }
        }
        __syncthreads();
        #pragma unroll
        for (int m = 0; m < ENC_M; m++) {
            float S = ssum[m * 4] + ssum[m * 4 + 1] + ssum[m * 4 + 2] + ssum[m * 4 + 3];
            float Q = ssq [m * 4] + ssq [m * 4 + 1] + ssq [m * 4 + 2] + ssq [m * 4 + 3];
            float mu  = S * (1.f / 128.f);
            float var = Q * (1.f / 128.f) - mu * mu;
            float inv = rsqrtf(var + 1e-5f);
            float v = gm * (acc[m] - mu) * inv + bt;
            v = gelu_f(v);
            int n = base + m;
            if (n < NND) h16[n * 128 + tid] = __float2half_rn(v);
        }
        __syncthreads();
    }
}

// ---------------- propagation step (warp per node, fp16 scaled state) ----------------
__global__ void __launch_bounds__(256) prop16_k(
    const uint2* __restrict__ z, const uint2* __restrict__ x0, uint2* __restrict__ o,
    const float4* __restrict__ gamma4, const float4* __restrict__ beta4,
    float cA, float cX, int fuse)
{
    int w = (blockIdx.x * blockDim.x + threadIdx.x) >> 5;
    int lane = threadIdx.x & 31;
    if (w >= NND) return;
    int beg = g_rowptr[w], end = g_rowptr[w + 1];

    float4 acc = make_float4(0.f, 0.f, 0.f, 0.f);
    int e = beg;
    for (; e + 8 <= end; e += 8) {
        EdgeP p0 = g_ep[e],     p1 = g_ep[e + 1], p2 = g_ep[e + 2], p3 = g_ep[e + 3];
        EdgeP p4 = g_ep[e + 4], p5 = g_ep[e + 5], p6 = g_ep[e + 6], p7 = g_ep[e + 7];
        uint2 u0 = z[p0.src * 32 + lane];
        uint2 u1 = z[p1.src * 32 + lane];
        uint2 u2 = z[p2.src * 32 + lane];
        uint2 u3 = z[p3.src * 32 + lane];
        uint2 u4 = z[p4.src * 32 + lane];
        uint2 u5 = z[p5.src * 32 + lane];
        uint2 u6 = z[p6.src * 32 + lane];
        uint2 u7 = z[p7.src * 32 + lane];
        fma16(acc, u0, p0.w); fma16(acc, u1, p1.w);
        fma16(acc, u2, p2.w); fma16(acc, u3, p3.w);
        fma16(acc, u4, p4.w); fma16(acc, u5, p5.w);
        fma16(acc, u6, p6.w); fma16(acc, u7, p7.w);
    }
    if (e + 4 <= end) {
        EdgeP p0 = g_ep[e], p1 = g_ep[e + 1], p2 = g_ep[e + 2], p3 = g_ep[e + 3];
        uint2 u0 = z[p0.src * 32 + lane];
        uint2 u1 = z[p1.src * 32 + lane];
        uint2 u2 = z[p2.src * 32 + lane];
        uint2 u3 = z[p3.src * 32 + lane];
        fma16(acc, u0, p0.w); fma16(acc, u1, p1.w);
        fma16(acc, u2, p2.w); fma16(acc, u3, p3.w);
        e += 4;
    }
    for (; e < end; e++) {
        EdgeP p = g_ep[e];
        uint2 u = z[p.src * 32 + lane];
        fma16(acc, u, p.w);
    }

    float4 xv = ld16(x0, w, lane);
    float4 r;
    r.x = cA * acc.x + cX * xv.x;
    r.y = cA * acc.y + cX * xv.y;
    r.z = cA * acc.z + cX * xv.z;
    r.w = cA * acc.w + cX * xv.w;

    if (fuse) {
        const float FS = 1073741824.0f;   // 8^10 = 2^30, exact
        r.x = gelu_f(r.x * FS); r.y = gelu_f(r.y * FS);
        r.z = gelu_f(r.z * FS); r.w = gelu_f(r.w * FS);
        float s = r.x + r.y + r.z + r.w;
        #pragma unroll
        for (int off = 16; off; off >>= 1)
            s += __shfl_xor_sync(0xffffffffu, s, off);
        float mu = s * (1.f / 128.f);
        float dx = r.x - mu, dy = r.y - mu, dz = r.z - mu, dw = r.w - mu;
        float q = dx * dx + dy * dy + dz * dz + dw * dw;
        #pragma unroll
        for (int off = 16; off; off >>= 1)
            q += __shfl_xor_sync(0xffffffffu, q, off);
        float var = q * (1.f / 128.f);
        float inv = rsqrtf(var + 1e-5f);
        float4 gmv = gamma4[lane], btv = beta4[lane];
        r.x = gmv.x * dx * inv + btv.x;
        r.y = gmv.y * dy * inv + btv.y;
        r.z = gmv.z * dz * inv + btv.z;
        r.w = gmv.w * dw * inv + btv.w;
    }
    st16(o, w, lane, r);
}

// ---------------- decoder (wmma): out = h16 @ Wdec^T ----------------
// 256 thr = 8 warps; tile 128 nodes x 64 cols; a-frags straight from global h16.
__global__ void __launch_bounds__(256) decoder_wmma_k(
    const float* __restrict__ Wd, float* __restrict__ out)
{
    __shared__ __half sWd[OUTC * 128];   // row-major, 16KB
    const int tid = threadIdx.x, wid = tid >> 5;
    for (int i = tid; i < OUTC * 128; i += 256) sWd[i] = __float2half_rn(Wd[i]);
    __syncthreads();

    const __half* h = (const __half*)g_h16;

    for (int tile = blockIdx.x; tile < NTILE; tile += gridDim.x) {
        const int row0 = tile * 128 + wid * 16;
        wmma::fragment<wmma::accumulator, 16, 16, 16, float> acc[4];
        #pragma unroll
        for (int nf = 0; nf < 4; nf++) wmma::fill_fragment(acc[nf], 0.f);
        #pragma unroll
        for (int k0 = 0; k0 < 8; k0++) {
            wmma::fragment<wmma::matrix_a, 16, 16, 16, __half, wmma::row_major> a;
            wmma::load_matrix_sync(a, h + row0 * 128 + k0 * 16, 128);
            #pragma unroll
            for (int nf = 0; nf < 4; nf++) {
                wmma::fragment<wmma::matrix_b, 16, 16, 16, __half, wmma::col_major> b;
                wmma::load_matrix_sync(b, sWd + (nf * 16) * 128 + k0 * 16, 128);
                wmma::mma_sync(acc[nf], a, b, acc[nf]);
            }
        }
        #pragma unroll
        for (int nf = 0; nf < 4; nf++)
            wmma::store_matrix_sync(out + row0 * 64 + nf * 16, acc[nf], 64,
                                    wmma::mem_row_major);
    }
}

// ---------------- scalar decoder (tail nodes) ----------------
__global__ void __launch_bounds__(256) decoder_k(
    const float* __restrict__ Wd, float* __restrict__ out, int start)
{
    __shared__ __align__(16) float sW[OUTC * 132];
    __shared__ __align__(16) float sx[4 * 128];
    const int tid = threadIdx.x;
    for (int i = tid; i < OUTC * HID; i += 256) {
        int c = i >> 7, k = i & 127;
        sW[c * 132 + k] = Wd[i];
    }
    __syncthreads();
    const int sub = tid >> 6, c = tid & 63;

    for (int base = start + blockIdx.x * 4; base < NND; base += gridDim.x * 4) {
        if (tid < 128) {
            int m = tid >> 5, ll = tid & 31;
            int n = base + m;
            float4 v = (n < NND) ? ld16(g_h16, n, ll)
                                 : make_float4(0.f, 0.f, 0.f, 0.f);
            *(float4*)(sx + m * 128 + ll * 4) = v;
        }
        __syncthreads();
        float acc = 0.f;
        #pragma unroll 4
        for (int k = 0; k < 128; k += 4) {
            float4 w4 = *(const float4*)(sW + c * 132 + k);
            float4 xv = *(const float4*)(sx + sub * 128 + k);
            acc += w4.x * xv.x + w4.y * xv.y + w4.z * xv.z + w4.w * xv.w;
        }
        int n = base + sub;
        if (n < NND) out[n * 64 + c] = acc;
        __syncthreads();
    }
}

// ---------------- launch ----------------
extern "C" void kernel_launch(void* const* d_in, const int* in_sizes, int n_in,
                              void* d_out, int out_size)
{
    const float* x     = (const float*)d_in[0];
    const void*  ei    = (const void*) d_in[1];
    const float* ew    = (const float*)d_in[2];
    const float* Wenc  = (const float*)d_in[3];
    const float* Wdec  = (const float*)d_in[4];
    const float* gamma = (const float*)d_in[5];
    const float* beta  = (const float*)d_in[6];
    float* out = (float*)d_out;

    void *ph, *pza, *pzb;
    cudaGetSymbolAddress(&ph,  g_h16);
    cudaGetSymbolAddress(&pza, g_za);
    cudaGetSymbolAddress(&pzb, g_zb);
    uint2* h16 = (uint2*)ph;
    uint2* za  = (uint2*)pza;
    uint2* zb  = (uint2*)pzb;

    const int NB_SCAN = (NND + 1023) / 1024;   // 98

    // ---- fork: CSR build on side stream, encoder on main stream ----
    cudaEventRecord(g_si.e1, 0);
    cudaStreamWaitEvent(g_si.s, g_si.e1, 0);

    zero_detect_k<<<(NND + 255) / 256, 256, 0, g_si.s>>>((const int*)ei);
    hist_k<<<(NE + 255) / 256, 256, 0, g_si.s>>>(ei);
    scan1_k<<<NB_SCAN, 1024, 0, g_si.s>>>();
    scan2_k<<<1, 32, 0, g_si.s>>>(NB_SCAN);
    scan3_k<<<(NND + 255) / 256, 256, 0, g_si.s>>>();
    fill_k<<<(NE + 255) / 256, 256, 0, g_si.s>>>(ei, ew);
    cudaEventRecord(g_si.e2, g_si.s);

    // encoder: wmma main + scalar tail
    int wenc_smem = 32768 + 65536;   // W16 + max(x16, C)
    cudaFuncSetAttribute(encoder_wmma_k, cudaFuncAttributeMaxDynamicSharedMemorySize, wenc_smem);
    encoder_wmma_k<<<296, 256, wenc_smem>>>(x, Wenc, gamma, beta);
    int enc_smem = (128 * 132 + ENC_M * 128 + ENC_M * 8) * (int)sizeof(float);
    cudaFuncSetAttribute(encoder_k, cudaFuncAttributeMaxDynamicSharedMemorySize, enc_smem);
    encoder_k<<<4, 128, enc_smem>>>(x, Wenc, gamma, beta, TAIL_START);

    // ---- join: prop needs both CSR and encoder output ----
    cudaStreamWaitEvent(0, g_si.e2, 0);

    const float4* g4 = (const float4*)gamma;
    const float4* b4 = (const float4*)beta;
    const int pblocks = (NND * 32) / 256;      // 12500

    const float cA = 0.9f / 8.0f;
    float cX[10];
    {
        float p = 1.0f;
        for (int k = 0; k < 10; k++) { p *= 0.125f; cX[k] = 0.1f * p; }
    }

    for (int layer = 0; layer < 4; layer++) {
        prop16_k<<<pblocks, 256>>>(h16, h16, za, g4, b4, cA, cX[0], 0);
        for (int k = 1; k < 9; k++) {
            const uint2* in = (k & 1) ? za : zb;
            uint2*       o  = (k & 1) ? zb : za;
            prop16_k<<<pblocks, 256>>>(in, h16, o, g4, b4, cA, cX[k], 0);
        }
        prop16_k<<<pblocks, 256>>>(za, h16, h16, g4, b4, cA, cX[9], 1);
    }

    decoder_wmma_k<<<781, 256>>>(Wdec, out);
    decoder_k<<<8, 256>>>(Wdec, out, TAIL_START);
}